// round 7
// baseline (speedup 1.0000x reference)
#include <cuda_runtime.h>
#include <cstdint>

#define NC        6
#define NWARPS    8
#define TPB       256
#define NBLOCKS   1036   // 148 SMs * 7 (smem-limited to 7 CTAs/SM)
#define NVALS     13     // ht[6], hp[6], dsum
#define CHUNK_ROWS 512   // rows per block-chunk (2 per thread)
#define F4_PER_CHUNK (CHUNK_ROWS * NC / 4)   // 768 float4 = 12 KB
#define I2_PER_CHUNK (CHUNK_ROWS / 2)        // 256 int2   = 2 KB

// Per-block partials, [val][block]; fully overwritten each launch.
__device__ unsigned int g_part[NVALS][NBLOCKS];
__device__ unsigned int g_ticket;   // last-block-done counter; reset by last block

__device__ __forceinline__ void cp_async16(uint32_t dst, const void* src) {
    asm volatile("cp.async.cg.shared.global [%0], [%1], 16;\n" :: "r"(dst), "l"(src));
}
__device__ __forceinline__ void cp_async8(uint32_t dst, const void* src) {
    asm volatile("cp.async.ca.shared.global [%0], [%1], 8;\n" :: "r"(dst), "l"(src));
}
__device__ __forceinline__ void cp_commit() {
    asm volatile("cp.async.commit_group;\n" ::: "memory");
}
template <int N>
__device__ __forceinline__ void cp_wait() {
    asm volatile("cp.async.wait_group %0;\n" :: "n"(N) : "memory");
}

__global__ void __launch_bounds__(TPB) kappa_fused_kernel(
    const float* __restrict__ yp,
    const int* __restrict__ yt,     // y_true is int32 (JAX x64-demotion)
    int n,
    float* __restrict__ out)
{
    __shared__ float4 sp[2][F4_PER_CHUNK];   // 24 KB
    __shared__ int2   sl[2][I2_PER_CHUNK];   // 4 KB

    const int tid  = threadIdx.x;
    const int warp = tid >> 5;
    const int lane = tid & 31;

    // Register accumulators: packed 6x10-bit histograms + squared-diff sum.
    unsigned long long ht_pack = 0ull;
    unsigned long long hp_pack = 0ull;
    unsigned int dsum = 0u;

    const float4* yp4 = (const float4*)yp;
    const int2*   yt2 = (const int2*)yt;
    const int nchunks = n / CHUNK_ROWS;

    const uint32_t sp_base = (uint32_t)__cvta_generic_to_shared(&sp[0][0]);
    const uint32_t sl_base = (uint32_t)__cvta_generic_to_shared(&sl[0][0]);

    // --- prefetch helper (as lambda-ish macro via code dup) ---
#define PREFETCH(c, b)                                                         \
    do {                                                                       \
        const size_t gf4 = (size_t)(c) * F4_PER_CHUNK;                         \
        cp_async16(sp_base + ((b) * F4_PER_CHUNK + tid          ) * 16,        \
                   &yp4[gf4 + tid]);                                           \
        cp_async16(sp_base + ((b) * F4_PER_CHUNK + tid + 256    ) * 16,        \
                   &yp4[gf4 + tid + 256]);                                     \
        cp_async16(sp_base + ((b) * F4_PER_CHUNK + tid + 512    ) * 16,        \
                   &yp4[gf4 + tid + 512]);                                     \
        cp_async8 (sl_base + ((b) * I2_PER_CHUNK + tid) * 8,                   \
                   &yt2[(size_t)(c) * I2_PER_CHUNK + tid]);                    \
    } while (0)

    int c   = blockIdx.x;
    int buf = 0;
    bool havecur = (c < nchunks);
    if (havecur) PREFETCH(c, 0);
    cp_commit();

    while (havecur) {
        const int  cn       = c + gridDim.x;
        const bool havenext = (cn < nchunks);
        if (havenext) PREFETCH(cn, buf ^ 1);
        cp_commit();

        cp_wait<1>();       // current buffer's group done
        __syncthreads();    // visible to whole block

        // Process 2 rows from smem: float4 indices 3*tid .. 3*tid+2
        // (stride-3 float4 reads tile all 32 banks per quarter-warp: conflict-free)
        {
            float4 f0 = sp[buf][3 * tid + 0];
            float4 f1 = sp[buf][3 * tid + 1];
            float4 f2 = sp[buf][3 * tid + 2];
            int2   t2 = sl[buf][tid];

            float v[12];
            v[0]=f0.x; v[1]=f0.y; v[2]=f0.z;  v[3]=f0.w;
            v[4]=f1.x; v[5]=f1.y; v[6]=f1.z;  v[7]=f1.w;
            v[8]=f2.x; v[9]=f2.y; v[10]=f2.z; v[11]=f2.w;

            int tt[2];
            tt[0] = t2.x; tt[1] = t2.y;

            #pragma unroll
            for (int r = 0; r < 2; r++) {
                const int base = r * 6;
                float bv = v[base];
                int   bi = 0;
                #pragma unroll
                for (int cc = 1; cc < 6; cc++) {
                    // strict > keeps FIRST max, matching jnp.argmax tie-break
                    if (v[base + cc] > bv) { bv = v[base + cc]; bi = cc; }
                }
                const int t = tt[r];
                const int d = t - bi;
                dsum    += (unsigned)(d * d);
                ht_pack += 1ull << (t  * 10);
                hp_pack += 1ull << (bi * 10);
            }
        }

        __syncthreads();    // done reading buf before it is re-prefetched
        c = cn; buf ^= 1; havecur = havenext;
    }
    cp_wait<0>();

    // Tail rows (n % 512): block 0, up to 2 rows per thread, direct loads.
    if (blockIdx.x == 0) {
        const int tbase = nchunks * CHUNK_ROWS;
        for (int r = tbase + tid; r < n; r += TPB) {
            const float* row = yp + (size_t)r * 6;
            float bv = row[0];
            int   bi = 0;
            #pragma unroll
            for (int cc = 1; cc < 6; cc++) {
                float x = row[cc];
                if (x > bv) { bv = x; bi = cc; }
            }
            const int t = yt[r];
            const int d = t - bi;
            dsum    += (unsigned)(d * d);
            ht_pack += 1ull << (t  * 10);
            hp_pack += 1ull << (bi * 10);
        }
    }

    // Unpack to 13 u32 and warp shuffle-reduce.
    unsigned int vals[NVALS];
    #pragma unroll
    for (int cc = 0; cc < NC; cc++) {
        vals[cc]      = (unsigned int)((ht_pack >> (cc * 10)) & 0x3FFu);
        vals[NC + cc] = (unsigned int)((hp_pack >> (cc * 10)) & 0x3FFu);
    }
    vals[12] = dsum;

    #pragma unroll
    for (int k = 0; k < NVALS; k++) {
        unsigned int s = vals[k];
        #pragma unroll
        for (int o = 16; o; o >>= 1)
            s += __shfl_xor_sync(0xffffffffu, s, o);
        vals[k] = s;
    }

    // Block merge via shared: lane 0 of each warp deposits its 13 sums.
    __shared__ unsigned int s_w[NWARPS][NVALS];
    if (lane == 0) {
        #pragma unroll
        for (int k = 0; k < NVALS; k++) s_w[warp][k] = vals[k];
    }
    __syncthreads();
    if (tid < NVALS) {
        unsigned int s = 0;
        #pragma unroll
        for (int w = 0; w < NWARPS; w++) s += s_w[w][tid];
        g_part[tid][blockIdx.x] = s;
    }
    __threadfence();   // release partials
    __syncthreads();

    // Last-block-done: final reduce + kappa.
    __shared__ unsigned int s_last;
    __shared__ unsigned int s_acc[NVALS];
    if (tid == 0)
        s_last = (atomicAdd(&g_ticket, 1u) == (unsigned)(gridDim.x - 1)) ? 1u : 0u;
    __syncthreads();
    if (!s_last) return;

    __threadfence();   // acquire: all blocks' partials visible

    if (tid < NVALS) s_acc[tid] = 0u;
    __syncthreads();

    // 13 values x 19 slices = 247 active threads.
    {
        const int k     = tid % NVALS;
        const int slice = tid / NVALS;
        if (slice < 19) {
            volatile const unsigned int* row = &g_part[k][0];
            unsigned int s = 0;
            for (int b = slice; b < NBLOCKS; b += 19) s += row[b];
            atomicAdd(&s_acc[k], s);
        }
    }
    __syncthreads();

    if (tid == 0) {
        double ht[NC], hp[NC];
        #pragma unroll
        for (int cc = 0; cc < NC; cc++) {
            ht[cc] = (double)s_acc[cc];
            hp[cc] = (double)s_acc[NC + cc];
        }
        const double num = (double)s_acc[12];   // sum W*conf (unnormalized)
        double den = 0.0;
        #pragma unroll
        for (int i = 0; i < NC; i++)
            #pragma unroll
            for (int j = 0; j < NC; j++)
                den += (double)((i - j) * (i - j)) * ht[i] * hp[j];
        const double N = (double)n;
        out[0] = (float)(1.0 - (num * N) / den);
        g_ticket = 0u;   // reset for next graph replay (deterministic)
    }
#undef PREFETCH
}

extern "C" void kernel_launch(void* const* d_in, const int* in_sizes, int n_in,
                              void* d_out, int out_size) {
    const float* yp  = (const float*)d_in[0];
    const int*   yt  = (const int*)d_in[1];
    float*       out = (float*)d_out;
    const int n = in_sizes[1];   // number of rows (y_true element count)

    kappa_fused_kernel<<<NBLOCKS, TPB>>>(yp, yt, n, out);
}

// round 8
// speedup vs baseline: 1.0155x; 1.0155x over previous
#include <cuda_runtime.h>
#include <cstdint>

#define NC         6
#define NWARPS     8
#define TPB        256
#define NBLOCKS    888    // 148 SMs * 6 (36KB smem/CTA -> 6 CTAs/SM)
#define NVALS      13     // ht[6], hp[6], dsum
#define NSTAGE     3
#define CHUNK_ROWS 512
#define F4_PER_CHUNK (CHUNK_ROWS * NC / 4)          // 768 float4 = 12 KB
#define CHUNK_BYTES  (CHUNK_ROWS * NC * 4)          // 12288

// Per-block partials, [val][block]; fully overwritten each launch.
__device__ unsigned int g_part[NVALS][NBLOCKS];
__device__ unsigned int g_ticket;   // last-block-done counter; reset by last block

__device__ __forceinline__ uint32_t smem_u32(const void* p) {
    return (uint32_t)__cvta_generic_to_shared(p);
}
__device__ __forceinline__ void mbar_init(uint32_t mbar, uint32_t count) {
    asm volatile("mbarrier.init.shared.b64 [%0], %1;" :: "r"(mbar), "r"(count) : "memory");
}
__device__ __forceinline__ void mbar_expect_tx(uint32_t mbar, uint32_t bytes) {
    asm volatile("mbarrier.arrive.expect_tx.shared.b64 _, [%0], %1;"
                 :: "r"(mbar), "r"(bytes) : "memory");
}
__device__ __forceinline__ void mbar_wait(uint32_t mbar, uint32_t parity) {
    uint32_t done;
    asm volatile(
        "{\n\t.reg .pred p;\n\t"
        "mbarrier.try_wait.parity.acquire.cta.shared::cta.b64 p, [%1], %2;\n\t"
        "selp.b32 %0, 1, 0, p;\n\t}"
        : "=r"(done) : "r"(mbar), "r"(parity) : "memory");
    if (!done) {
        asm volatile(
            "{\n\t.reg .pred P1;\n\t"
            "WAIT_LOOP_%=:\n\t"
            "mbarrier.try_wait.parity.acquire.cta.shared::cta.b64 P1, [%0], %1, 0x989680;\n\t"
            "@P1 bra.uni WAIT_DONE_%=;\n\t"
            "bra.uni WAIT_LOOP_%=;\n\t"
            "WAIT_DONE_%=:\n\t}"
            :: "r"(mbar), "r"(parity) : "memory");
    }
}
__device__ __forceinline__ void bulk_ld(uint32_t dst, const void* src,
                                        uint32_t bytes, uint32_t mbar) {
    asm volatile(
        "cp.async.bulk.shared::cluster.global.mbarrier::complete_tx::bytes "
        "[%0], [%1], %2, [%3];"
        :: "r"(dst), "l"(src), "r"(bytes), "r"(mbar) : "memory");
}

__global__ void __launch_bounds__(TPB) kappa_fused_kernel(
    const float* __restrict__ yp,
    const int* __restrict__ yt,     // y_true is int32 (JAX x64-demotion)
    int n,
    float* __restrict__ out)
{
    __shared__ float4 sp[NSTAGE][F4_PER_CHUNK];                  // 36 KB
    __shared__ __align__(8) unsigned long long mbar_s[NSTAGE];

    const int tid  = threadIdx.x;
    const int warp = tid >> 5;
    const int lane = tid & 31;

    uint32_t mb[NSTAGE];
    #pragma unroll
    for (int s = 0; s < NSTAGE; s++) mb[s] = smem_u32(&mbar_s[s]);

    if (tid == 0) {
        #pragma unroll
        for (int s = 0; s < NSTAGE; s++) mbar_init(mb[s], 1);
    }
    __syncthreads();

    // Register accumulators: packed 6x10-bit histograms + squared-diff sum.
    unsigned long long ht_pack = 0ull;
    unsigned long long hp_pack = 0ull;
    unsigned int dsum = 0u;

    const int2* yt2 = (const int2*)yt;
    const int nchunks = n / CHUNK_ROWS;
    const int bid  = blockIdx.x;
    const int grid = gridDim.x;

    // Prologue: issue chunks k=0..NSTAGE-2 (slot = k % NSTAGE = k).
    if (tid == 0) {
        #pragma unroll
        for (int k = 0; k < NSTAGE - 1; k++) {
            const int c = bid + k * grid;
            if (c < nchunks) {
                mbar_expect_tx(mb[k], CHUNK_BYTES);
                bulk_ld(smem_u32(&sp[k][0]),
                        (const char*)yp + (size_t)c * CHUNK_BYTES,
                        CHUNK_BYTES, mb[k]);
            }
        }
    }

    for (int k = 0; ; k++) {
        const int c = bid + k * grid;
        if (c >= nchunks) break;
        const int slot = k % NSTAGE;

        // One sync: orders (a) last iter's reads of slot (k-1)%NSTAGE before
        // its re-fill below, (b) everything before this iter's mbar wait.
        __syncthreads();

        // Prefetch chunk k+NSTAGE-1 into slot (k-1)%NSTAGE (distance 2 chunks).
        if (tid == 0) {
            const int cp = bid + (k + NSTAGE - 1) * grid;
            if (cp < nchunks) {
                const int ps = (k + NSTAGE - 1) % NSTAGE;
                mbar_expect_tx(mb[ps], CHUNK_BYTES);
                bulk_ld(smem_u32(&sp[ps][0]),
                        (const char*)yp + (size_t)cp * CHUNK_BYTES,
                        CHUNK_BYTES, mb[ps]);
            }
        }

        // Labels: direct coalesced LDG.64 (inflation-1 already), overlaps wait.
        const int2 t2 = yt2[(size_t)c * (CHUNK_ROWS / 2) + tid];

        // Wait chunk k: mbar[slot], (k/NSTAGE)-th use -> parity (k/NSTAGE)&1.
        mbar_wait(mb[slot], (unsigned)(k / NSTAGE) & 1u);

        // Process 2 rows: float4 indices 3*tid..3*tid+2 (conflict-free LDS).
        {
            float4 f0 = sp[slot][3 * tid + 0];
            float4 f1 = sp[slot][3 * tid + 1];
            float4 f2 = sp[slot][3 * tid + 2];

            float v[12];
            v[0]=f0.x; v[1]=f0.y; v[2]=f0.z;  v[3]=f0.w;
            v[4]=f1.x; v[5]=f1.y; v[6]=f1.z;  v[7]=f1.w;
            v[8]=f2.x; v[9]=f2.y; v[10]=f2.z; v[11]=f2.w;

            int tt[2];
            tt[0] = t2.x; tt[1] = t2.y;

            #pragma unroll
            for (int r = 0; r < 2; r++) {
                const int base = r * 6;
                float bv = v[base];
                int   bi = 0;
                #pragma unroll
                for (int cc = 1; cc < 6; cc++) {
                    // strict > keeps FIRST max, matching jnp.argmax tie-break
                    if (v[base + cc] > bv) { bv = v[base + cc]; bi = cc; }
                }
                const int t = tt[r];
                const int d = t - bi;
                dsum    += (unsigned)(d * d);
                ht_pack += 1ull << (t  * 10);
                hp_pack += 1ull << (bi * 10);
            }
        }
    }

    // Tail rows (n % 512): block 0, direct loads.
    if (blockIdx.x == 0) {
        const int tbase = nchunks * CHUNK_ROWS;
        for (int r = tbase + tid; r < n; r += TPB) {
            const float* row = yp + (size_t)r * 6;
            float bv = row[0];
            int   bi = 0;
            #pragma unroll
            for (int cc = 1; cc < 6; cc++) {
                float x = row[cc];
                if (x > bv) { bv = x; bi = cc; }
            }
            const int t = yt[r];
            const int d = t - bi;
            dsum    += (unsigned)(d * d);
            ht_pack += 1ull << (t  * 10);
            hp_pack += 1ull << (bi * 10);
        }
    }

    // Unpack to 13 u32 and warp shuffle-reduce.
    unsigned int vals[NVALS];
    #pragma unroll
    for (int cc = 0; cc < NC; cc++) {
        vals[cc]      = (unsigned int)((ht_pack >> (cc * 10)) & 0x3FFu);
        vals[NC + cc] = (unsigned int)((hp_pack >> (cc * 10)) & 0x3FFu);
    }
    vals[12] = dsum;

    #pragma unroll
    for (int k = 0; k < NVALS; k++) {
        unsigned int s = vals[k];
        #pragma unroll
        for (int o = 16; o; o >>= 1)
            s += __shfl_xor_sync(0xffffffffu, s, o);
        vals[k] = s;
    }

    // Block merge via shared: lane 0 of each warp deposits its 13 sums.
    __shared__ unsigned int s_w[NWARPS][NVALS];
    if (lane == 0) {
        #pragma unroll
        for (int k = 0; k < NVALS; k++) s_w[warp][k] = vals[k];
    }
    __syncthreads();
    if (tid < NVALS) {
        unsigned int s = 0;
        #pragma unroll
        for (int w = 0; w < NWARPS; w++) s += s_w[w][tid];
        g_part[tid][blockIdx.x] = s;
    }
    __threadfence();   // release partials
    __syncthreads();

    // Last-block-done: final reduce + kappa.
    __shared__ unsigned int s_last;
    __shared__ unsigned int s_acc[NVALS];
    if (tid == 0)
        s_last = (atomicAdd(&g_ticket, 1u) == (unsigned)(gridDim.x - 1)) ? 1u : 0u;
    __syncthreads();
    if (!s_last) return;

    __threadfence();   // acquire: all blocks' partials visible

    if (tid < NVALS) s_acc[tid] = 0u;
    __syncthreads();

    // 13 values x 19 slices = 247 active threads.
    {
        const int k     = tid % NVALS;
        const int slice = tid / NVALS;
        if (slice < 19) {
            volatile const unsigned int* row = &g_part[k][0];
            unsigned int s = 0;
            for (int b = slice; b < NBLOCKS; b += 19) s += row[b];
            atomicAdd(&s_acc[k], s);
        }
    }
    __syncthreads();

    if (tid == 0) {
        double ht[NC], hp[NC];
        #pragma unroll
        for (int cc = 0; cc < NC; cc++) {
            ht[cc] = (double)s_acc[cc];
            hp[cc] = (double)s_acc[NC + cc];
        }
        const double num = (double)s_acc[12];   // sum W*conf (unnormalized)
        double den = 0.0;
        #pragma unroll
        for (int i = 0; i < NC; i++)
            #pragma unroll
            for (int j = 0; j < NC; j++)
                den += (double)((i - j) * (i - j)) * ht[i] * hp[j];
        const double N = (double)n;
        out[0] = (float)(1.0 - (num * N) / den);
        g_ticket = 0u;   // reset for next graph replay (deterministic)
    }
}

extern "C" void kernel_launch(void* const* d_in, const int* in_sizes, int n_in,
                              void* d_out, int out_size) {
    const float* yp  = (const float*)d_in[0];
    const int*   yt  = (const int*)d_in[1];
    float*       out = (float*)d_out;
    const int n = in_sizes[1];   // number of rows (y_true element count)

    kappa_fused_kernel<<<NBLOCKS, TPB>>>(yp, yt, n, out);
}

// round 9
// speedup vs baseline: 1.1393x; 1.1219x over previous
#include <cuda_runtime.h>

#define NC      6
#define NWARPS  8
#define TPB     256
#define NBLOCKS 1184   // 148 SMs * 8
#define NVALS   13     // ht[6], hp[6], dsum

// Per-block partials, [val][block]; fully overwritten each launch.
__device__ unsigned int g_part[NVALS][NBLOCKS];
__device__ unsigned int g_ticket;   // last-block-done counter; reset by last block

__global__ void __launch_bounds__(TPB) kappa_fused_kernel(
    const float* __restrict__ yp,
    const int* __restrict__ yt,     // y_true is int32 (JAX x64-demotion)
    int n,
    float* __restrict__ out)
{
    const int tid  = threadIdx.x;
    const int warp = tid >> 5;
    const int lane = tid & 31;

    // Register accumulators: packed 6x10-bit histograms + squared-diff sum.
    unsigned long long ht_pack = 0ull;
    unsigned long long hp_pack = 0ull;
    unsigned int dsum = 0u;

    const int ngroups = n >> 1;                   // groups of 2 rows
    const float4* yp4 = (const float4*)yp;        // 3 float4 per group (12 floats)
    const int2*   yt2 = (const int2*)yt;          // 1 int2 per group (2 labels)
    const int stride = gridDim.x * blockDim.x;

    int g = blockIdx.x * blockDim.x + tid;

    // Paired iterations: 6 independent LDG.128 + 2 LDG.64 in flight before any
    // consumption -> 2x per-warp MLP vs single-group loop.
    for (; g + stride < ngroups; g += 2 * stride) {
        const int g2 = g + stride;
        float4 a0 = __ldcg(&yp4[(size_t)g  * 3 + 0]);
        float4 a1 = __ldcg(&yp4[(size_t)g  * 3 + 1]);
        float4 a2 = __ldcg(&yp4[(size_t)g  * 3 + 2]);
        float4 b0 = __ldcg(&yp4[(size_t)g2 * 3 + 0]);
        float4 b1 = __ldcg(&yp4[(size_t)g2 * 3 + 1]);
        float4 b2 = __ldcg(&yp4[(size_t)g2 * 3 + 2]);
        int2   ta = __ldcg(&yt2[g]);
        int2   tb = __ldcg(&yt2[g2]);

        float v[24];
        v[0]=a0.x;  v[1]=a0.y;  v[2]=a0.z;  v[3]=a0.w;
        v[4]=a1.x;  v[5]=a1.y;  v[6]=a1.z;  v[7]=a1.w;
        v[8]=a2.x;  v[9]=a2.y;  v[10]=a2.z; v[11]=a2.w;
        v[12]=b0.x; v[13]=b0.y; v[14]=b0.z; v[15]=b0.w;
        v[16]=b1.x; v[17]=b1.y; v[18]=b1.z; v[19]=b1.w;
        v[20]=b2.x; v[21]=b2.y; v[22]=b2.z; v[23]=b2.w;

        int tt[4];
        tt[0] = ta.x; tt[1] = ta.y; tt[2] = tb.x; tt[3] = tb.y;

        #pragma unroll
        for (int r = 0; r < 4; r++) {
            const int base = r * 6;
            float bv = v[base];
            int   bi = 0;
            #pragma unroll
            for (int c = 1; c < 6; c++) {
                // strict > keeps FIRST max, matching jnp.argmax tie-break
                if (v[base + c] > bv) { bv = v[base + c]; bi = c; }
            }
            const int t = tt[r];
            const int d = t - bi;
            dsum    += (unsigned)(d * d);
            ht_pack += 1ull << (t  * 10);
            hp_pack += 1ull << (bi * 10);
        }
    }

    // Remaining single iteration (each thread has at most one left).
    if (g < ngroups) {
        float4 f0 = __ldcg(&yp4[(size_t)g * 3 + 0]);
        float4 f1 = __ldcg(&yp4[(size_t)g * 3 + 1]);
        float4 f2 = __ldcg(&yp4[(size_t)g * 3 + 2]);
        int2   t2 = __ldcg(&yt2[g]);

        float v[12];
        v[0]=f0.x; v[1]=f0.y; v[2]=f0.z;  v[3]=f0.w;
        v[4]=f1.x; v[5]=f1.y; v[6]=f1.z;  v[7]=f1.w;
        v[8]=f2.x; v[9]=f2.y; v[10]=f2.z; v[11]=f2.w;

        int tt[2];
        tt[0] = t2.x; tt[1] = t2.y;

        #pragma unroll
        for (int r = 0; r < 2; r++) {
            const int base = r * 6;
            float bv = v[base];
            int   bi = 0;
            #pragma unroll
            for (int c = 1; c < 6; c++) {
                if (v[base + c] > bv) { bv = v[base + c]; bi = c; }
            }
            const int t = tt[r];
            const int d = t - bi;
            dsum    += (unsigned)(d * d);
            ht_pack += 1ull << (t  * 10);
            hp_pack += 1ull << (bi * 10);
        }
    }

    // Tail row (n odd): block 0, thread 0.
    if (blockIdx.x == 0 && tid == 0 && (n & 1)) {
        const int r = n - 1;
        const float* row = yp + (size_t)r * 6;
        float bv = row[0];
        int   bi = 0;
        #pragma unroll
        for (int c = 1; c < 6; c++) {
            float x = row[c];
            if (x > bv) { bv = x; bi = c; }
        }
        const int t = yt[r];
        const int d = t - bi;
        dsum    += (unsigned)(d * d);
        ht_pack += 1ull << (t  * 10);
        hp_pack += 1ull << (bi * 10);
    }

    // Unpack to 13 u32 and warp shuffle-reduce.
    unsigned int vals[NVALS];
    #pragma unroll
    for (int c = 0; c < NC; c++) {
        vals[c]      = (unsigned int)((ht_pack >> (c * 10)) & 0x3FFu);
        vals[NC + c] = (unsigned int)((hp_pack >> (c * 10)) & 0x3FFu);
    }
    vals[12] = dsum;

    #pragma unroll
    for (int k = 0; k < NVALS; k++) {
        unsigned int s = vals[k];
        #pragma unroll
        for (int o = 16; o; o >>= 1)
            s += __shfl_xor_sync(0xffffffffu, s, o);
        vals[k] = s;
    }

    // Block merge via shared: lane 0 of each warp deposits its 13 sums.
    __shared__ unsigned int s_w[NWARPS][NVALS];
    if (lane == 0) {
        #pragma unroll
        for (int k = 0; k < NVALS; k++) s_w[warp][k] = vals[k];
    }
    __syncthreads();
    if (tid < NVALS) {
        unsigned int s = 0;
        #pragma unroll
        for (int w = 0; w < NWARPS; w++) s += s_w[w][tid];
        g_part[tid][blockIdx.x] = s;
    }
    __threadfence();   // release partials
    __syncthreads();

    // Last-block-done: final reduce + kappa.
    __shared__ unsigned int s_last;
    __shared__ unsigned int s_acc[NVALS];
    if (tid == 0)
        s_last = (atomicAdd(&g_ticket, 1u) == (unsigned)(gridDim.x - 1)) ? 1u : 0u;
    __syncthreads();
    if (!s_last) return;

    __threadfence();   // acquire: all blocks' partials visible

    if (tid < NVALS) s_acc[tid] = 0u;
    __syncthreads();

    // 13 values x 19 slices = 247 active threads.
    {
        const int k     = tid % NVALS;
        const int slice = tid / NVALS;
        if (slice < 19) {
            volatile const unsigned int* row = &g_part[k][0];
            unsigned int s = 0;
            for (int b = slice; b < NBLOCKS; b += 19) s += row[b];
            atomicAdd(&s_acc[k], s);
        }
    }
    __syncthreads();

    if (tid == 0) {
        double ht[NC], hp[NC];
        #pragma unroll
        for (int c = 0; c < NC; c++) {
            ht[c] = (double)s_acc[c];
            hp[c] = (double)s_acc[NC + c];
        }
        const double num = (double)s_acc[12];   // sum W*conf (unnormalized)
        double den = 0.0;
        #pragma unroll
        for (int i = 0; i < NC; i++)
            #pragma unroll
            for (int j = 0; j < NC; j++)
                den += (double)((i - j) * (i - j)) * ht[i] * hp[j];
        const double N = (double)n;
        out[0] = (float)(1.0 - (num * N) / den);
        g_ticket = 0u;   // reset for next graph replay (deterministic)
    }
}

extern "C" void kernel_launch(void* const* d_in, const int* in_sizes, int n_in,
                              void* d_out, int out_size) {
    const float* yp  = (const float*)d_in[0];
    const int*   yt  = (const int*)d_in[1];
    float*       out = (float*)d_out;
    const int n = in_sizes[1];   // number of rows (y_true element count)

    kappa_fused_kernel<<<NBLOCKS, TPB>>>(yp, yt, n, out);
}

// round 10
// speedup vs baseline: 1.2347x; 1.0837x over previous
#include <cuda_runtime.h>

#define NC      6
#define NWARPS  8
#define TPB     256
#define NBLOCKS 592    // 148 SMs * 4 (4 CTAs/SM -> 64 regs/thread budget)
#define NVALS   13     // ht[6], hp[6], dsum

// Per-block partials, [val][block]; fully overwritten each launch.
__device__ unsigned int g_part[NVALS][NBLOCKS];
__device__ unsigned int g_ticket;   // last-block-done counter; reset by last block

__device__ __forceinline__ void process_group(
    float4 f0, float4 f1, float4 f2, int2 t2,
    unsigned long long& ht_pack, unsigned long long& hp_pack, unsigned int& dsum)
{
    float v[12];
    v[0]=f0.x; v[1]=f0.y; v[2]=f0.z;  v[3]=f0.w;
    v[4]=f1.x; v[5]=f1.y; v[6]=f1.z;  v[7]=f1.w;
    v[8]=f2.x; v[9]=f2.y; v[10]=f2.z; v[11]=f2.w;

    int tt[2];
    tt[0] = t2.x; tt[1] = t2.y;

    #pragma unroll
    for (int r = 0; r < 2; r++) {
        const int base = r * 6;
        float bv = v[base];
        int   bi = 0;
        #pragma unroll
        for (int c = 1; c < 6; c++) {
            // strict > keeps FIRST max, matching jnp.argmax tie-break
            if (v[base + c] > bv) { bv = v[base + c]; bi = c; }
        }
        const int t = tt[r];
        const int d = t - bi;
        dsum    += (unsigned)(d * d);
        ht_pack += 1ull << (t  * 10);
        hp_pack += 1ull << (bi * 10);
    }
}

__global__ void __launch_bounds__(TPB, 4) kappa_fused_kernel(
    const float* __restrict__ yp,
    const int* __restrict__ yt,     // y_true is int32 (JAX x64-demotion)
    int n,
    float* __restrict__ out)
{
    const int tid  = threadIdx.x;
    const int warp = tid >> 5;
    const int lane = tid & 31;

    // Register accumulators: packed 6x10-bit histograms + squared-diff sum.
    unsigned long long ht_pack = 0ull;
    unsigned long long hp_pack = 0ull;
    unsigned int dsum = 0u;

    const int ngroups = n >> 1;                   // groups of 2 rows
    const float4* yp4 = (const float4*)yp;        // 3 float4 per group (12 floats)
    const int2*   yt2 = (const int2*)yt;          // 1 int2 per group (2 labels)
    const int stride = gridDim.x * blockDim.x;

    // Software pipeline, prefetch distance 1: next group's loads are issued
    // BEFORE the current group is consumed, keeping them in flight across the
    // whole consume phase (forces MLP ~= 2 iterations of loads outstanding).
    int g = blockIdx.x * blockDim.x + tid;
    bool have = (g < ngroups);

    float4 c0, c1, c2; int2 ct;
    if (have) {
        c0 = __ldcg(&yp4[(size_t)g * 3 + 0]);
        c1 = __ldcg(&yp4[(size_t)g * 3 + 1]);
        c2 = __ldcg(&yp4[(size_t)g * 3 + 2]);
        ct = __ldcg(&yt2[g]);
    }

    while (have) {
        const int  gn    = g + stride;
        const bool haven = (gn < ngroups);

        float4 n0, n1, n2; int2 nt;
        if (haven) {
            n0 = __ldcg(&yp4[(size_t)gn * 3 + 0]);
            n1 = __ldcg(&yp4[(size_t)gn * 3 + 1]);
            n2 = __ldcg(&yp4[(size_t)gn * 3 + 2]);
            nt = __ldcg(&yt2[gn]);
        }

        process_group(c0, c1, c2, ct, ht_pack, hp_pack, dsum);

        c0 = n0; c1 = n1; c2 = n2; ct = nt;
        g = gn; have = haven;
    }

    // Tail row (n odd): block 0, thread 0.
    if (blockIdx.x == 0 && tid == 0 && (n & 1)) {
        const int r = n - 1;
        const float* row = yp + (size_t)r * 6;
        float bv = row[0];
        int   bi = 0;
        #pragma unroll
        for (int c = 1; c < 6; c++) {
            float x = row[c];
            if (x > bv) { bv = x; bi = c; }
        }
        const int t = yt[r];
        const int d = t - bi;
        dsum    += (unsigned)(d * d);
        ht_pack += 1ull << (t  * 10);
        hp_pack += 1ull << (bi * 10);
    }

    // Unpack to 13 u32 and warp shuffle-reduce.
    unsigned int vals[NVALS];
    #pragma unroll
    for (int c = 0; c < NC; c++) {
        vals[c]      = (unsigned int)((ht_pack >> (c * 10)) & 0x3FFu);
        vals[NC + c] = (unsigned int)((hp_pack >> (c * 10)) & 0x3FFu);
    }
    vals[12] = dsum;

    #pragma unroll
    for (int k = 0; k < NVALS; k++) {
        unsigned int s = vals[k];
        #pragma unroll
        for (int o = 16; o; o >>= 1)
            s += __shfl_xor_sync(0xffffffffu, s, o);
        vals[k] = s;
    }

    // Block merge via shared: lane 0 of each warp deposits its 13 sums.
    __shared__ unsigned int s_w[NWARPS][NVALS];
    if (lane == 0) {
        #pragma unroll
        for (int k = 0; k < NVALS; k++) s_w[warp][k] = vals[k];
    }
    __syncthreads();
    if (tid < NVALS) {
        unsigned int s = 0;
        #pragma unroll
        for (int w = 0; w < NWARPS; w++) s += s_w[w][tid];
        g_part[tid][blockIdx.x] = s;
    }
    __threadfence();   // release partials
    __syncthreads();

    // Last-block-done: final reduce + kappa.
    __shared__ unsigned int s_last;
    __shared__ unsigned int s_acc[NVALS];
    if (tid == 0)
        s_last = (atomicAdd(&g_ticket, 1u) == (unsigned)(gridDim.x - 1)) ? 1u : 0u;
    __syncthreads();
    if (!s_last) return;

    __threadfence();   // acquire: all blocks' partials visible

    if (tid < NVALS) s_acc[tid] = 0u;
    __syncthreads();

    // 13 values x 19 slices = 247 active threads.
    {
        const int k     = tid % NVALS;
        const int slice = tid / NVALS;
        if (slice < 19) {
            volatile const unsigned int* row = &g_part[k][0];
            unsigned int s = 0;
            for (int b = slice; b < NBLOCKS; b += 19) s += row[b];
            atomicAdd(&s_acc[k], s);
        }
    }
    __syncthreads();

    if (tid == 0) {
        double ht[NC], hp[NC];
        #pragma unroll
        for (int c = 0; c < NC; c++) {
            ht[c] = (double)s_acc[c];
            hp[c] = (double)s_acc[NC + c];
        }
        const double num = (double)s_acc[12];   // sum W*conf (unnormalized)
        double den = 0.0;
        #pragma unroll
        for (int i = 0; i < NC; i++)
            #pragma unroll
            for (int j = 0; j < NC; j++)
                den += (double)((i - j) * (i - j)) * ht[i] * hp[j];
        const double N = (double)n;
        out[0] = (float)(1.0 - (num * N) / den);
        g_ticket = 0u;   // reset for next graph replay (deterministic)
    }
}

extern "C" void kernel_launch(void* const* d_in, const int* in_sizes, int n_in,
                              void* d_out, int out_size) {
    const float* yp  = (const float*)d_in[0];
    const int*   yt  = (const int*)d_in[1];
    float*       out = (float*)d_out;
    const int n = in_sizes[1];   // number of rows (y_true element count)

    kappa_fused_kernel<<<NBLOCKS, TPB>>>(yp, yt, n, out);
}